// round 2
// baseline (speedup 1.0000x reference)
#include <cuda_runtime.h>

// Problem constants
#define NB   512      // batches
#define NL   512      // stream length
#define NC   8        // channels
#define NSEG 4        // stream segments (Chen-associative split)
#define SEGLEN 128    // increments per segment (last has 127)
#define SIGSZ 584     // 8 + 64 + 512
#define NINC (NL - 1) // 511

// Scratch for per-segment partial signatures: [batch][seg][584]
__device__ float g_part[(size_t)NB * NSEG * SIGSZ];

using u64 = unsigned long long;

// ---- f32x2 packed helpers (sm_103a FFMA2 path; ptxas won't emit from C++) ----
__device__ __forceinline__ u64 pk2(float a, float b) {
    u64 r; asm("mov.b64 %0,{%1,%2};" : "=l"(r) : "f"(a), "f"(b)); return r;
}
__device__ __forceinline__ void upk2(u64 v, float& a, float& b) {
    asm("mov.b64 {%0,%1},%2;" : "=f"(a), "=f"(b) : "l"(v));
}
__device__ __forceinline__ u64 f2mul(u64 a, u64 b) {
    u64 r; asm("mul.rn.f32x2 %0,%1,%2;" : "=l"(r) : "l"(a), "l"(b)); return r;
}
__device__ __forceinline__ u64 f2add(u64 a, u64 b) {
    u64 r; asm("add.rn.f32x2 %0,%1,%2;" : "=l"(r) : "l"(a), "l"(b)); return r;
}
__device__ __forceinline__ u64 f2fma(u64 a, u64 b, u64 c) {
    u64 r; asm("fma.rn.f32x2 %0,%1,%2,%3;" : "=l"(r) : "l"(a), "l"(b), "l"(c)); return r;
}

// ---------------------------------------------------------------------------
// Segment kernel: 1 block = 1 warp = one (batch, segment) task.
// Lane t owns i = t>>2, pairs (i, j0) and (i, j0+1) with j0 = (t&3)*2.
// Packed state: S1h2 = {S1[i]/2, S1[i]/2}, S22 = {S2[i,j0], S2[i,j0+1]},
// S3p[p][kk] = {S3[i,j0+p,2kk], S3[i,j0+p,2kk+1]}.
// Per-step (old state on RHS):
//   coeff[i,j] = dx_i dx_j/6 + (S1/2)[i] dx_j + S2[i,j]
//   S3[i,j,k] += coeff * dx_k        (8 FFMA2 covers 16 pairs-of-k)
//   S2 += dx_i dx_j/2 + S1[i] dx_j ; S1/2 += dx_i/2
// ---------------------------------------------------------------------------
__global__ __launch_bounds__(32) void seg_kernel(const float* __restrict__ path) {
    __shared__ __align__(16) float spath[(64 + 1) * NC];  // raw path rows for one chunk
    __shared__ __align__(16) float sdx[64 * NC];          // increments for one chunk

    const int t  = threadIdx.x;
    const int i  = t >> 2;
    const int j0 = (t & 3) << 1;

    const int task  = blockIdx.x;          // 0..2047
    const int batch = task >> 2;
    const int seg   = task & 3;
    const int t0    = seg * SEGLEN;
    const int nsteps = (seg == NSEG - 1) ? (NINC - (NSEG - 1) * SEGLEN) : SEGLEN; // 127/128

    const float* __restrict__ pb = path + (size_t)batch * NL * NC;

    const u64 C16 = pk2(1.f / 6.f, 1.f / 6.f);
    const u64 CH  = pk2(0.5f, 0.5f);
    const u64 C2  = pk2(2.f, 2.f);

    u64 S1h2 = 0ull;
    u64 S22  = 0ull;
    u64 S3p[2][4];
    #pragma unroll
    for (int p = 0; p < 2; p++)
        #pragma unroll
        for (int k = 0; k < 4; k++) S3p[p][k] = 0ull;

    for (int c0 = 0; c0 < nsteps; c0 += 64) {
        const int Tc = min(64, nsteps - c0);

        __syncthreads();  // previous chunk's step loop done reading sdx
        // stage (Tc+1) path rows as float4s (coalesced)
        {
            const float4* __restrict__ gp =
                (const float4*)(pb + (size_t)(t0 + c0) * NC);
            const int n4 = (Tc + 1) * 2;
            for (int v = t; v < n4; v += 32) ((float4*)spath)[v] = gp[v];
        }
        __syncthreads();
        // increments
        for (int e = t; e < Tc * NC; e += 32) sdx[e] = spath[e + NC] - spath[e];
        __syncthreads();

        #pragma unroll 4
        for (int s = 0; s < Tc; s++) {
            const u64* __restrict__ drow = (const u64*)(sdx + s * NC);
            const u64 d01 = drow[0];
            const u64 d23 = drow[1];
            const u64 d45 = drow[2];
            const u64 d67 = drow[3];
            const float dxi = sdx[s * NC + i];
            const u64 dxj01 = *(const u64*)(sdx + s * NC + j0);

            const u64 dxi2 = pk2(dxi, dxi);
            const u64 aa = f2mul(dxi2, dxj01);            // {dxi*dxj0, dxi*dxj1}
            const u64 bb = f2mul(S1h2, dxj01);            // {S1h*dxj0, S1h*dxj1}
            const u64 cf2 = f2fma(aa, C16, f2add(bb, S22));
            float c0f, c1f; upk2(cf2, c0f, c1f);
            const u64 c00 = pk2(c0f, c0f);
            const u64 c11 = pk2(c1f, c1f);

            S3p[0][0] = f2fma(c00, d01, S3p[0][0]);
            S3p[0][1] = f2fma(c00, d23, S3p[0][1]);
            S3p[0][2] = f2fma(c00, d45, S3p[0][2]);
            S3p[0][3] = f2fma(c00, d67, S3p[0][3]);
            S3p[1][0] = f2fma(c11, d01, S3p[1][0]);
            S3p[1][1] = f2fma(c11, d23, S3p[1][1]);
            S3p[1][2] = f2fma(c11, d45, S3p[1][2]);
            S3p[1][3] = f2fma(c11, d67, S3p[1][3]);

            S22  = f2fma(aa, CH, f2fma(bb, C2, S22));
            S1h2 = f2fma(dxi2, CH, S1h2);
        }
    }

    // epilogue: write partial signature
    float* __restrict__ op = g_part + (size_t)task * SIGSZ;
    float s1lo, s1hi; upk2(S1h2, s1lo, s1hi);
    if ((t & 3) == 0) op[i] = 2.f * s1lo;
    *(u64*)(op + 8 + i * 8 + j0) = S22;  // two packed S2 floats
    {
        u64* __restrict__ o3 = (u64*)(op + 72 + (i * 8 + j0) * 8);
        o3[0] = S3p[0][0]; o3[1] = S3p[0][1]; o3[2] = S3p[0][2]; o3[3] = S3p[0][3];
        u64* __restrict__ o3b = (u64*)(op + 72 + (i * 8 + j0 + 1) * 8);
        o3b[0] = S3p[1][0]; o3b[1] = S3p[1][1]; o3b[2] = S3p[1][2]; o3b[3] = S3p[1][3];
    }
}

// ---------------------------------------------------------------------------
// Combine kernel: per batch, fold 4 segment signatures with Chen's identity.
// All B-segment data (3 x 27 floats/thread) prefetched into registers first
// so the L2 latency is paid once (high MLP), then 3 folds of pure FMA.
// ---------------------------------------------------------------------------
__global__ __launch_bounds__(64) void combine_kernel(float* __restrict__ out) {
    const int w = threadIdx.x;
    const int i = w >> 3;
    const int j = w & 7;
    const int batch = blockIdx.x;

    const float* __restrict__ p0 = g_part + (size_t)batch * NSEG * SIGSZ;

    // A = segment 0
    float A1 = p0[i];
    float A2 = p0[8 + w];
    float A3[8];
    {
        float4 a = *(const float4*)(p0 + 72 + w * 8);
        float4 b = *(const float4*)(p0 + 72 + w * 8 + 4);
        A3[0] = a.x; A3[1] = a.y; A3[2] = a.z; A3[3] = a.w;
        A3[4] = b.x; A3[5] = b.y; A3[6] = b.z; A3[7] = b.w;
    }

    // Prefetch all three B segments (independent loads -> high MLP)
    float B1i[3], B1j[3], B2ij[3];
    float b1[3][8], b2[3][8], b3[3][8];
    #pragma unroll
    for (int s = 0; s < 3; s++) {
        const float* __restrict__ pp = p0 + (s + 1) * SIGSZ;
        B1i[s]  = pp[i];
        B1j[s]  = pp[j];
        B2ij[s] = pp[8 + w];
        float4 x0 = *(const float4*)(pp);
        float4 x1 = *(const float4*)(pp + 4);
        b1[s][0] = x0.x; b1[s][1] = x0.y; b1[s][2] = x0.z; b1[s][3] = x0.w;
        b1[s][4] = x1.x; b1[s][5] = x1.y; b1[s][6] = x1.z; b1[s][7] = x1.w;
        float4 y0 = *(const float4*)(pp + 8 + j * 8);
        float4 y1 = *(const float4*)(pp + 8 + j * 8 + 4);
        b2[s][0] = y0.x; b2[s][1] = y0.y; b2[s][2] = y0.z; b2[s][3] = y0.w;
        b2[s][4] = y1.x; b2[s][5] = y1.y; b2[s][6] = y1.z; b2[s][7] = y1.w;
        float4 z0 = *(const float4*)(pp + 72 + w * 8);
        float4 z1 = *(const float4*)(pp + 72 + w * 8 + 4);
        b3[s][0] = z0.x; b3[s][1] = z0.y; b3[s][2] = z0.z; b3[s][3] = z0.w;
        b3[s][4] = z1.x; b3[s][5] = z1.y; b3[s][6] = z1.z; b3[s][7] = z1.w;
    }

    // Sequential Chen folds (uses OLD A1/A2 on RHS)
    #pragma unroll
    for (int s = 0; s < 3; s++) {
        #pragma unroll
        for (int k = 0; k < 8; k++)
            A3[k] = fmaf(A1, b2[s][k], fmaf(A2, b1[s][k], A3[k] + b3[s][k]));
        A2 = fmaf(A1, B1j[s], A2 + B2ij[s]);
        A1 = A1 + B1i[s];
    }

    float* __restrict__ ob = out + (size_t)batch * SIGSZ;
    if (j == 0) ob[i] = A1;
    ob[8 + w] = A2;
    *(float4*)(ob + 72 + w * 8)     = make_float4(A3[0], A3[1], A3[2], A3[3]);
    *(float4*)(ob + 72 + w * 8 + 4) = make_float4(A3[4], A3[5], A3[6], A3[7]);
}

extern "C" void kernel_launch(void* const* d_in, const int* in_sizes, int n_in,
                              void* d_out, int out_size) {
    const float* path = (const float*)d_in[0];
    float* out = (float*)d_out;
    seg_kernel<<<NB * NSEG, 32>>>(path);     // 2048 one-warp blocks
    combine_kernel<<<NB, 64>>>(out);
}

// round 3
// speedup vs baseline: 1.2412x; 1.2412x over previous
#include <cuda_runtime.h>

// Problem constants
#define NB   512      // batches
#define NL   512      // stream length
#define NC   8        // channels
#define NSEG 8        // stream segments (Chen-associative split)
#define SEGLEN 64     // increments per segment (last has 63)
#define SIGSZ 584     // 8 + 64 + 512
#define NINC (NL - 1) // 511

// Scratch for per-segment partial signatures: [batch][seg][584] = 9.56 MB
__device__ float g_part[(size_t)NB * NSEG * SIGSZ];

// ---------------------------------------------------------------------------
// Segment kernel: 2 tasks per 128-thread block; 64-thread group = one
// (batch, segment). Thread w = i*8+j owns S1[i]/2, S2[i,j], S3[i,j,0..7].
//
// Per-step update (old S1h, S2 on RHS), FFMA-imm-heavy form:
//   m     = dxi/6 + S1h                (FFMA-imm, rt=1)
//   coeff = dxj*m + S2                 ( = S2 + dxi*dxj/6 + S1h*dxj )
//   n     = 3*m - S1h                  (FFMA-imm;  = dxi/2 + S1)
//   S2   += dxj*n                      ( = S2 + dxi*dxj/2 + S1*dxj )
//   S3[k]+= coeff * dx_k               (8 FMAs, dx from two LDS.128)
//   S1h  += dxi/2                      (FFMA-imm)
// 13 FMA-pipe ops/thread-step, 4 of them imm-form.
// ---------------------------------------------------------------------------
__global__ __launch_bounds__(128) void seg_kernel(const float* __restrict__ path) {
    __shared__ __align__(16) float sdx[2][SEGLEN * NC];   // [task-in-block][step][chan]

    const int tid  = threadIdx.x;
    const int g    = tid >> 6;          // task slot in block (0/1)
    const int w    = tid & 63;          // lane within task
    const int i    = w >> 3;
    const int j    = w & 7;

    const int task  = blockIdx.x * 2 + g;      // 0..4095
    const int batch = task >> 3;               // 0..511
    const int seg   = task & 7;                // 0..7
    const int t0    = seg * SEGLEN;
    const int nsteps = (seg == NSEG - 1) ? (NINC - (NSEG - 1) * SEGLEN) : SEGLEN; // 63/64

    const float* __restrict__ pb = path + (size_t)batch * NL * NC + (size_t)t0 * NC;

    // Stage increments for the whole segment (one chunk), then one sync.
    for (int e = w; e < nsteps * NC; e += 64)
        sdx[g][e] = pb[e + NC] - pb[e];
    __syncthreads();

    float S1h = 0.f;   // S1[i] / 2
    float S2  = 0.f;   // S2[i,j]
    float S3[8];
    #pragma unroll
    for (int k = 0; k < 8; k++) S3[k] = 0.f;

    const float* __restrict__ dxp = sdx[g];
    #pragma unroll 4
    for (int t = 0; t < nsteps; t++) {
        const float4 d0 = *(const float4*)(dxp + t * 8);
        const float4 d1 = *(const float4*)(dxp + t * 8 + 4);
        const float dxi = dxp[t * 8 + i];
        const float dxj = dxp[t * 8 + j];

        const float m     = fmaf(dxi, 0.16666666666666666f, S1h);
        const float coeff = fmaf(dxj, m, S2);
        const float n     = fmaf(3.0f, m, -S1h);   // dxi/2 + S1
        S2 = fmaf(dxj, n, S2);

        S3[0] = fmaf(coeff, d0.x, S3[0]);
        S3[1] = fmaf(coeff, d0.y, S3[1]);
        S3[2] = fmaf(coeff, d0.z, S3[2]);
        S3[3] = fmaf(coeff, d0.w, S3[3]);
        S3[4] = fmaf(coeff, d1.x, S3[4]);
        S3[5] = fmaf(coeff, d1.y, S3[5]);
        S3[6] = fmaf(coeff, d1.z, S3[6]);
        S3[7] = fmaf(coeff, d1.w, S3[7]);

        S1h = fmaf(0.5f, dxi, S1h);
    }

    float* __restrict__ op = g_part + (size_t)task * SIGSZ;
    if (j == 0) op[i] = 2.f * S1h;
    op[8 + w] = S2;
    *(float4*)(op + 72 + w * 8)     = make_float4(S3[0], S3[1], S3[2], S3[3]);
    *(float4*)(op + 72 + w * 8 + 4) = make_float4(S3[4], S3[5], S3[6], S3[7]);
}

// ---------------------------------------------------------------------------
// Combine kernel: per batch, fold the 8 segment signatures left-to-right with
// Chen's identity:
//   S1 = A1 + B1
//   S2 = A2 + B2 + A1 (x) B1
//   S3 = A3 + B3 + A1 (x) B2 + A2 (x) B1
// Thread w = i*8+j holds A1[i], A2[i,j], A3[i,j,0..7].
// ---------------------------------------------------------------------------
__global__ __launch_bounds__(64) void combine_kernel(float* __restrict__ out) {
    const int w = threadIdx.x;
    const int i = w >> 3;
    const int j = w & 7;
    const int batch = blockIdx.x;

    const float* __restrict__ p0 = g_part + (size_t)batch * NSEG * SIGSZ;

    float A1 = p0[i];
    float A2 = p0[8 + w];
    float A3[8];
    {
        float4 a = *(const float4*)(p0 + 72 + w * 8);
        float4 b = *(const float4*)(p0 + 72 + w * 8 + 4);
        A3[0] = a.x; A3[1] = a.y; A3[2] = a.z; A3[3] = a.w;
        A3[4] = b.x; A3[5] = b.y; A3[6] = b.z; A3[7] = b.w;
    }

    #pragma unroll
    for (int s = 1; s < NSEG; s++) {
        const float* __restrict__ pp = p0 + s * SIGSZ;
        const float B1i  = pp[i];
        const float B1j  = pp[j];
        const float B2ij = pp[8 + w];
        float4 x0 = *(const float4*)(pp);
        float4 x1 = *(const float4*)(pp + 4);
        float4 y0 = *(const float4*)(pp + 8 + j * 8);       // B2[j, 0..3]
        float4 y1 = *(const float4*)(pp + 8 + j * 8 + 4);   // B2[j, 4..7]
        float4 z0 = *(const float4*)(pp + 72 + w * 8);
        float4 z1 = *(const float4*)(pp + 72 + w * 8 + 4);

        float b1v[8] = {x0.x, x0.y, x0.z, x0.w, x1.x, x1.y, x1.z, x1.w};
        float b2v[8] = {y0.x, y0.y, y0.z, y0.w, y1.x, y1.y, y1.z, y1.w};
        float b3v[8] = {z0.x, z0.y, z0.z, z0.w, z1.x, z1.y, z1.z, z1.w};

        #pragma unroll
        for (int k = 0; k < 8; k++)   // uses OLD A1, A2
            A3[k] = fmaf(A1, b2v[k], fmaf(A2, b1v[k], A3[k] + b3v[k]));
        A2 = fmaf(A1, B1j, A2 + B2ij);   // old A1
        A1 = A1 + B1i;
    }

    float* __restrict__ ob = out + (size_t)batch * SIGSZ;
    if (j == 0) ob[i] = A1;
    ob[8 + w] = A2;
    *(float4*)(ob + 72 + w * 8)     = make_float4(A3[0], A3[1], A3[2], A3[3]);
    *(float4*)(ob + 72 + w * 8 + 4) = make_float4(A3[4], A3[5], A3[6], A3[7]);
}

extern "C" void kernel_launch(void* const* d_in, const int* in_sizes, int n_in,
                              void* d_out, int out_size) {
    const float* path = (const float*)d_in[0];
    float* out = (float*)d_out;
    seg_kernel<<<(NB * NSEG) / 2, 128>>>(path);   // 2048 blocks, 2 tasks each
    combine_kernel<<<NB, 64>>>(out);
}

// round 4
// speedup vs baseline: 1.3653x; 1.1000x over previous
#include <cuda_runtime.h>

// Problem constants
#define NB   512      // batches
#define NL   512      // stream length
#define NC   8        // channels
#define NSEG 4        // stream segments (Chen-associative split)
#define SEGLEN 128    // increments per segment (last has 127)
#define SIGSZ 584     // 8 + 64 + 512
#define NINC (NL - 1) // 511

// Scratch for per-segment partial signatures: [batch][seg][584]
__device__ float g_part[(size_t)NB * NSEG * SIGSZ];

// ---------------------------------------------------------------------------
// Segment kernel: 2 tasks per 128-thread block; 64-thread group = one
// (batch, segment). Thread w = i*8+j owns S1[i]/2, S2[i,j], S3[i,j,0..7].
// Per-step (old S1h, S2 on RHS):
//   m     = dxi/6 + S1h
//   coeff = dxj*m + S2        ( = S2 + S1h*dxj + dxi*dxj/6 )
//   n     = 3*m - S1h         ( = dxi/2 + S1 )
//   S2   += dxj*n
//   S3[k]+= coeff*dx_k  (8 FMAs, dx broadcast from shared)
//   S1h  += dxi/2
// ---------------------------------------------------------------------------
__global__ __launch_bounds__(128) void seg_kernel(const float* __restrict__ path) {
    __shared__ __align__(16) float sdx[2][SEGLEN * NC];   // 4 KB per task

    const int tid  = threadIdx.x;
    const int g    = tid >> 6;          // task slot in block (0/1)
    const int w    = tid & 63;
    const int i    = w >> 3;
    const int j    = w & 7;

    const int task  = blockIdx.x * 2 + g;      // 0..2047
    const int batch = task >> 2;
    const int seg   = task & 3;
    const int t0    = seg * SEGLEN;
    const int nsteps = (seg == NSEG - 1) ? (NINC - (NSEG - 1) * SEGLEN) : SEGLEN; // 127/128

    const float* __restrict__ pb = path + (size_t)batch * NL * NC + (size_t)t0 * NC;

    // Stage increments for the whole segment, one sync.
    for (int e = w; e < nsteps * NC; e += 64)
        sdx[g][e] = pb[e + NC] - pb[e];
    __syncthreads();

    float S1h = 0.f;
    float S2  = 0.f;
    float S3[8];
    #pragma unroll
    for (int k = 0; k < 8; k++) S3[k] = 0.f;

    const float* __restrict__ dxp = sdx[g];
    #pragma unroll 4
    for (int t = 0; t < nsteps; t++) {
        const float4 d0 = *(const float4*)(dxp + t * 8);
        const float4 d1 = *(const float4*)(dxp + t * 8 + 4);
        const float dxi = dxp[t * 8 + i];
        const float dxj = dxp[t * 8 + j];

        const float m     = fmaf(dxi, 0.16666666666666666f, S1h);
        const float coeff = fmaf(dxj, m, S2);
        const float n     = fmaf(3.0f, m, -S1h);
        S2 = fmaf(dxj, n, S2);

        S3[0] = fmaf(coeff, d0.x, S3[0]);
        S3[1] = fmaf(coeff, d0.y, S3[1]);
        S3[2] = fmaf(coeff, d0.z, S3[2]);
        S3[3] = fmaf(coeff, d0.w, S3[3]);
        S3[4] = fmaf(coeff, d1.x, S3[4]);
        S3[5] = fmaf(coeff, d1.y, S3[5]);
        S3[6] = fmaf(coeff, d1.z, S3[6]);
        S3[7] = fmaf(coeff, d1.w, S3[7]);

        S1h = fmaf(0.5f, dxi, S1h);
    }

    float* __restrict__ op = g_part + (size_t)task * SIGSZ;
    if (j == 0) op[i] = 2.f * S1h;
    op[8 + w] = S2;
    *(float4*)(op + 72 + w * 8)     = make_float4(S3[0], S3[1], S3[2], S3[3]);
    *(float4*)(op + 72 + w * 8 + 4) = make_float4(S3[4], S3[5], S3[6], S3[7]);
}

// ---------------------------------------------------------------------------
// Tree combine: 1 block = 1 batch, 256 threads = 4 groups of 64.
// Group g loads segment g's partial into registers (all loads parallel ->
// one L2 latency). Then 2 fold rounds:
//   round 1: g0 <- g0 o g1 (B via smem),  g2 <- g2 o g3
//   round 2: g0 <- g0 o g2
// Chen fold (old A on RHS): S3 += B3 + A1(x)B2 + A2(x)B1; S2 += B2 + A1(x)B1;
// S1 += B1.
// ---------------------------------------------------------------------------
struct SigRegs {
    float A1;     // A1[i]
    float A2;     // A2[i,j]
    float A3[8];  // A3[i,j,0..7]
};

__device__ __forceinline__ void sig_store_smem(float* __restrict__ sb,
                                               const SigRegs& S, int w, int i, int j) {
    if (j == 0) sb[i] = S.A1;
    sb[8 + w] = S.A2;
    *(float4*)(sb + 72 + w * 8)     = make_float4(S.A3[0], S.A3[1], S.A3[2], S.A3[3]);
    *(float4*)(sb + 72 + w * 8 + 4) = make_float4(S.A3[4], S.A3[5], S.A3[6], S.A3[7]);
}

__device__ __forceinline__ void sig_fold(SigRegs& S, const float* __restrict__ sb,
                                         int w, int i, int j) {
    const float B1i  = sb[i];
    const float B1j  = sb[j];
    const float B2ij = sb[8 + w];
    float4 x0 = *(const float4*)(sb);
    float4 x1 = *(const float4*)(sb + 4);
    float4 y0 = *(const float4*)(sb + 8 + j * 8);
    float4 y1 = *(const float4*)(sb + 8 + j * 8 + 4);
    float4 z0 = *(const float4*)(sb + 72 + w * 8);
    float4 z1 = *(const float4*)(sb + 72 + w * 8 + 4);

    float b1v[8] = {x0.x, x0.y, x0.z, x0.w, x1.x, x1.y, x1.z, x1.w};
    float b2v[8] = {y0.x, y0.y, y0.z, y0.w, y1.x, y1.y, y1.z, y1.w};
    float b3v[8] = {z0.x, z0.y, z0.z, z0.w, z1.x, z1.y, z1.z, z1.w};

    #pragma unroll
    for (int k = 0; k < 8; k++)  // uses OLD A1, A2
        S.A3[k] = fmaf(S.A1, b2v[k], fmaf(S.A2, b1v[k], S.A3[k] + b3v[k]));
    S.A2 = fmaf(S.A1, B1j, S.A2 + B2ij);
    S.A1 = S.A1 + B1i;
}

__global__ __launch_bounds__(256) void combine_kernel(float* __restrict__ out) {
    __shared__ __align__(16) float sb[NSEG][592];   // 592 pad (16-float aligned)

    const int tid = threadIdx.x;
    const int g   = tid >> 6;        // group = segment
    const int w   = tid & 63;
    const int i   = w >> 3;
    const int j   = w & 7;
    const int batch = blockIdx.x;

    const float* __restrict__ pp = g_part + (size_t)(batch * NSEG + g) * SIGSZ;

    SigRegs S;
    S.A1 = pp[i];
    S.A2 = pp[8 + w];
    {
        float4 a = *(const float4*)(pp + 72 + w * 8);
        float4 b = *(const float4*)(pp + 72 + w * 8 + 4);
        S.A3[0] = a.x; S.A3[1] = a.y; S.A3[2] = a.z; S.A3[3] = a.w;
        S.A3[4] = b.x; S.A3[5] = b.y; S.A3[6] = b.z; S.A3[7] = b.w;
    }

    // groups 1 and 3 publish their sig (they act as B in round 1)
    if (g == 1 || g == 3) sig_store_smem(sb[g], S, w, i, j);
    __syncthreads();

    // round 1: g0 <- g0 o g1 ; g2 <- g2 o g3
    if (g == 0) sig_fold(S, sb[1], w, i, j);
    if (g == 2) {
        sig_fold(S, sb[3], w, i, j);
        sig_store_smem(sb[2], S, w, i, j);
    }
    __syncthreads();

    // round 2: g0 <- g0 o g2 ; write out
    if (g == 0) {
        sig_fold(S, sb[2], w, i, j);
        float* __restrict__ ob = out + (size_t)batch * SIGSZ;
        if (j == 0) ob[i] = S.A1;
        ob[8 + w] = S.A2;
        *(float4*)(ob + 72 + w * 8)     = make_float4(S.A3[0], S.A3[1], S.A3[2], S.A3[3]);
        *(float4*)(ob + 72 + w * 8 + 4) = make_float4(S.A3[4], S.A3[5], S.A3[6], S.A3[7]);
    }
}

extern "C" void kernel_launch(void* const* d_in, const int* in_sizes, int n_in,
                              void* d_out, int out_size) {
    const float* path = (const float*)d_in[0];
    float* out = (float*)d_out;
    seg_kernel<<<(NB * NSEG) / 2, 128>>>(path);   // 1024 blocks, 2 tasks each
    combine_kernel<<<NB, 256>>>(out);             // 1 block per batch, tree fold
}

// round 7
// speedup vs baseline: 1.4985x; 1.0976x over previous
#include <cuda_runtime.h>

// Problem constants
#define NB   512      // batches
#define NL   512      // stream length
#define NC   8        // channels
#define NSEG 4        // segments per batch (Chen-associative split)
#define SEGLEN 128    // increments per segment (last has 127)
#define SIGSZ 584     // 8 + 64 + 512
#define NINC (NL - 1) // 511

// ---------------------------------------------------------------------------
// Fused signature kernel: 1 block = 1 batch, 256 threads = 4 groups of 64.
// Group g scans segment g (Thread w = i*8+j owns S1[i]/2, S2[i,j], S3[i,j,:]),
// then the 4 partial signatures are tree-folded in shared memory:
//   round 1: g0 <- g0 o g1,  g2 <- g2 o g3
//   round 2: g0 <- g0 o g2   -> write out
// Chen fold (old A on RHS): S3 += B3 + A1(x)B2 + A2(x)B1; S2 += B2 + A1(x)B1;
// S1 += B1.
// ---------------------------------------------------------------------------

struct SigRegs {
    float A1;     // A1[i]
    float A2;     // A2[i,j]
    float A3[8];  // A3[i,j,0..7]
};

__device__ __forceinline__ void sig_store_smem(float* __restrict__ sb,
                                               const SigRegs& S, int w, int i, int j) {
    if (j == 0) sb[i] = S.A1;
    sb[8 + w] = S.A2;
    *(float4*)(sb + 72 + w * 8)     = make_float4(S.A3[0], S.A3[1], S.A3[2], S.A3[3]);
    *(float4*)(sb + 72 + w * 8 + 4) = make_float4(S.A3[4], S.A3[5], S.A3[6], S.A3[7]);
}

__device__ __forceinline__ void sig_fold(SigRegs& S, const float* __restrict__ sb,
                                         int w, int i, int j) {
    const float B1i  = sb[i];
    const float B1j  = sb[j];
    const float B2ij = sb[8 + w];
    float4 x0 = *(const float4*)(sb);
    float4 x1 = *(const float4*)(sb + 4);
    float4 y0 = *(const float4*)(sb + 8 + j * 8);       // B2[j, 0..3]
    float4 y1 = *(const float4*)(sb + 8 + j * 8 + 4);   // B2[j, 4..7]
    float4 z0 = *(const float4*)(sb + 72 + w * 8);
    float4 z1 = *(const float4*)(sb + 72 + w * 8 + 4);

    float b1v[8] = {x0.x, x0.y, x0.z, x0.w, x1.x, x1.y, x1.z, x1.w};
    float b2v[8] = {y0.x, y0.y, y0.z, y0.w, y1.x, y1.y, y1.z, y1.w};
    float b3v[8] = {z0.x, z0.y, z0.z, z0.w, z1.x, z1.y, z1.z, z1.w};

    #pragma unroll
    for (int k = 0; k < 8; k++)  // uses OLD A1, A2
        S.A3[k] = fmaf(S.A1, b2v[k], fmaf(S.A2, b1v[k], S.A3[k] + b3v[k]));
    S.A2 = fmaf(S.A1, B1j, S.A2 + B2ij);
    S.A1 = S.A1 + B1i;
}

__global__ __launch_bounds__(256) void sig_kernel(const float* __restrict__ path,
                                                  float* __restrict__ out) {
    // 16 KB: per-group increment buffers; reused as fold buffers afterwards
    __shared__ __align__(16) float sdx[NSEG][SEGLEN * NC];

    const int tid = threadIdx.x;
    const int g   = tid >> 6;        // group = segment
    const int w   = tid & 63;
    const int i   = w >> 3;
    const int j   = w & 7;
    const int batch = blockIdx.x;
    const int t0    = g * SEGLEN;
    const int nsteps = (g == NSEG - 1) ? (NINC - (NSEG - 1) * SEGLEN) : SEGLEN; // 127/128

    // ---- stage increments for this group's segment ----
    const float* __restrict__ pb = path + (size_t)batch * NL * NC + (size_t)t0 * NC;
    for (int e = w; e < nsteps * NC; e += 64)
        sdx[g][e] = pb[e + NC] - pb[e];
    __syncthreads();

    // ---- sequential scan over this segment ----
    // Per step (old S1h, S2 on RHS):
    //   m = dxi/6 + S1h ; coeff = dxj*m + S2 ; n = 3m - S1h (= dxi/2 + S1)
    //   S2 += dxj*n ; S3[k] += coeff*dx_k ; S1h += dxi/2
    float S1h = 0.f;
    float S2  = 0.f;
    float S3[8];
    #pragma unroll
    for (int k = 0; k < 8; k++) S3[k] = 0.f;

    const float* __restrict__ dxp = sdx[g];
    #pragma unroll 4
    for (int t = 0; t < nsteps; t++) {
        const float4 d0 = *(const float4*)(dxp + t * 8);
        const float4 d1 = *(const float4*)(dxp + t * 8 + 4);
        const float dxi = dxp[t * 8 + i];
        const float dxj = dxp[t * 8 + j];

        const float m     = fmaf(dxi, 0.16666666666666666f, S1h);
        const float coeff = fmaf(dxj, m, S2);
        const float n     = fmaf(3.0f, m, -S1h);
        S2 = fmaf(dxj, n, S2);

        S3[0] = fmaf(coeff, d0.x, S3[0]);
        S3[1] = fmaf(coeff, d0.y, S3[1]);
        S3[2] = fmaf(coeff, d0.z, S3[2]);
        S3[3] = fmaf(coeff, d0.w, S3[3]);
        S3[4] = fmaf(coeff, d1.x, S3[4]);
        S3[5] = fmaf(coeff, d1.y, S3[5]);
        S3[6] = fmaf(coeff, d1.z, S3[6]);
        S3[7] = fmaf(coeff, d1.w, S3[7]);

        S1h = fmaf(0.5f, dxi, S1h);
    }

    SigRegs S;
    S.A1 = 2.f * S1h;
    S.A2 = S2;
    #pragma unroll
    for (int k = 0; k < 8; k++) S.A3[k] = S3[k];

    // ---- in-block tree fold (reuse sdx buffers as 584-float sig buffers) ----
    // Each group has finished reading its own sdx[g]; groups 1 & 3 now publish.
    if (g == 1 || g == 3) sig_store_smem(sdx[g], S, w, i, j);
    __syncthreads();

    // round 1: g0 <- g0 o g1 ; g2 <- g2 o g3 (g2 publishes result)
    if (g == 0) sig_fold(S, sdx[1], w, i, j);
    if (g == 2) {
        sig_fold(S, sdx[3], w, i, j);
        sig_store_smem(sdx[2], S, w, i, j);
    }
    __syncthreads();

    // round 2: g0 <- g0 o g2 ; write result
    if (g == 0) {
        sig_fold(S, sdx[2], w, i, j);
        float* __restrict__ ob = out + (size_t)batch * SIGSZ;
        if (j == 0) ob[i] = S.A1;
        ob[8 + w] = S.A2;
        *(float4*)(ob + 72 + w * 8)     = make_float4(S.A3[0], S.A3[1], S.A3[2], S.A3[3]);
        *(float4*)(ob + 72 + w * 8 + 4) = make_float4(S.A3[4], S.A3[5], S.A3[6], S.A3[7]);
    }
}

extern "C" void kernel_launch(void* const* d_in, const int* in_sizes, int n_in,
                              void* d_out, int out_size) {
    const float* path = (const float*)d_in[0];
    float* out = (float*)d_out;
    sig_kernel<<<NB, 256>>>(path, out);   // one block per batch, fully fused
}